// round 1
// baseline (speedup 1.0000x reference)
#include <cuda_runtime.h>
#include <cuda_bf16.h>
#include <cstdint>

#define NUM_CHR 24
#define N_EMB   512
#define DIM     512
#define BATCH   1024

// ---------------- scratch (no allocations allowed) ----------------
__device__ float g_W[BATCH * N_EMB];      // normalized RBF weights, [B, N]
__device__ int   g_order[BATCH];          // sample ids grouped by chromosome
__device__ int   g_start[NUM_CHR + 1];    // group offsets

// ---------------- f32x2 packed helpers ----------------
__device__ __forceinline__ unsigned long long pack2(float lo, float hi) {
    unsigned long long r;
    asm("mov.b64 %0, {%1, %2};" : "=l"(r) : "f"(lo), "f"(hi));
    return r;
}
__device__ __forceinline__ void unpack2(unsigned long long v, float& lo, float& hi) {
    asm("mov.b64 {%0, %1}, %2;" : "=f"(lo), "=f"(hi) : "l"(v));
}
__device__ __forceinline__ void ffma2(unsigned long long& d,
                                      unsigned long long a,
                                      unsigned long long b) {
    asm("fma.rn.f32x2 %0, %1, %2, %0;" : "+l"(d) : "l"(a), "l"(b));
}

// ---------------- kernel 1: normalized RBF weights ----------------
// grid = BATCH blocks, 128 threads; each thread handles 4 of the 512 centers.
__global__ void __launch_bounds__(128) weights_kernel(
    const int* __restrict__ chrom,
    const float* __restrict__ pos,
    const float* __restrict__ centers,
    const float* __restrict__ logv)
{
    int b = blockIdx.x;
    int c = chrom[b];
    float p = pos[b];
    int t = threadIdx.x;

    const float* crow = centers + (size_t)c * N_EMB;
    const float* vrow = logv + (size_t)c * N_EMB;

    float w[4];
    float s = 0.f;
#pragma unroll
    for (int i = 0; i < 4; i++) {
        int n = t + i * 128;
        float cc = crow[n];
        float vv = expf(vrow[n]);
        float d = p - cc;
        w[i] = expf(-(d * d) / (2.f * vv));
        s += w[i];
    }
    // warp reduce
#pragma unroll
    for (int off = 16; off > 0; off >>= 1)
        s += __shfl_down_sync(0xffffffffu, s, off);
    __shared__ float ws[4];
    int lane = t & 31, warp = t >> 5;
    if (lane == 0) ws[warp] = s;
    __syncthreads();
    float total = ws[0] + ws[1] + ws[2] + ws[3];
    float inv = 1.f / total;

    float* wrow = g_W + (size_t)b * N_EMB;
#pragma unroll
    for (int i = 0; i < 4; i++) {
        int n = t + i * 128;
        wrow[n] = w[i] * inv;
    }
}

// ---------------- kernel 2: group samples by chromosome ----------------
// single block, BATCH threads. Determinism of the OUTPUT is preserved even
// though atomic order varies: each sample's output depends only on its own row.
__global__ void group_kernel(const int* __restrict__ chrom)
{
    __shared__ int cnt[NUM_CHR];
    __shared__ int base[NUM_CHR];
    int t = threadIdx.x;
    if (t < NUM_CHR) cnt[t] = 0;
    __syncthreads();
    int c = chrom[t];
    int r = atomicAdd(&cnt[c], 1);
    __syncthreads();
    if (t == 0) {
        int acc = 0;
        for (int i = 0; i < NUM_CHR; i++) {
            base[i] = acc;
            g_start[i] = acc;
            acc += cnt[i];
        }
        g_start[NUM_CHR] = acc;  // == BATCH
    }
    __syncthreads();
    g_order[base[c] + r] = t;
}

// ---------------- kernel 3: grouped GEMM ----------------
// Per chromosome c: out[s, d] = sum_n W[s, n] * E[c, n, d] over its samples.
// Tiles: M_TILE=64 samples, N_TILE=128 dims, K chunks of 32.
// 128 threads, each computes an 8(m) x 8(n) micro-tile with f32x2 packed FMA.
#define M_TILE 64
#define N_TILE 128
#define KB 32

__global__ void __launch_bounds__(128) gemm_kernel(
    const float* __restrict__ E,
    float* __restrict__ out)
{
    int c  = blockIdx.z;
    int nt = blockIdx.x;
    int mt = blockIdx.y;

    int s0  = g_start[c];
    int cnt = g_start[c + 1] - s0;
    int m0  = mt * M_TILE;
    if (m0 >= cnt) return;

    __shared__ __align__(16) float As[KB][M_TILE];   // As[k][m] = W[sample m, k0+k]
    __shared__ __align__(16) float Bs[KB][N_TILE];   // Bs[k][n] = E[c, k0+k, d0+n]

    int tid = threadIdx.x;
    int d0  = nt * N_TILE;

    // A-load assignment: thread -> (sample row, 16-float half of the 32-chunk)
    int am = tid >> 1;            // 0..63
    int ah = (tid & 1) * 16;      // 0 or 16
    int gm = m0 + am;
    int samp = (gm < cnt) ? g_order[s0 + gm] : -1;
    const float* wrow = (samp >= 0) ? (g_W + (size_t)samp * N_EMB) : g_W;

    // B-load assignment: 8 float4 per thread
    int brow = tid >> 5;          // 0..3
    int bcol = (tid & 31) * 4;    // 0..124

    // micro-tile coords
    int tx = tid & 15;            // n-group: d = d0 + tx*8 .. +8
    int ty = tid >> 4;            // m-group: m = ty*8 .. +8

    unsigned long long acc[8][4];
#pragma unroll
    for (int i = 0; i < 8; i++)
#pragma unroll
        for (int j = 0; j < 4; j++) acc[i][j] = 0ull;  // (0.f, 0.f)

    for (int k0 = 0; k0 < N_EMB; k0 += KB) {
        // ---- load A tile (transposed) ----
        if (samp >= 0) {
            float4 v0 = *(const float4*)(wrow + k0 + ah + 0);
            float4 v1 = *(const float4*)(wrow + k0 + ah + 4);
            float4 v2 = *(const float4*)(wrow + k0 + ah + 8);
            float4 v3 = *(const float4*)(wrow + k0 + ah + 12);
            As[ah + 0][am] = v0.x;  As[ah + 1][am] = v0.y;
            As[ah + 2][am] = v0.z;  As[ah + 3][am] = v0.w;
            As[ah + 4][am] = v1.x;  As[ah + 5][am] = v1.y;
            As[ah + 6][am] = v1.z;  As[ah + 7][am] = v1.w;
            As[ah + 8][am] = v2.x;  As[ah + 9][am] = v2.y;
            As[ah + 10][am] = v2.z; As[ah + 11][am] = v2.w;
            As[ah + 12][am] = v3.x; As[ah + 13][am] = v3.y;
            As[ah + 14][am] = v3.z; As[ah + 15][am] = v3.w;
        } else {
#pragma unroll
            for (int j = 0; j < 16; j++) As[ah + j][am] = 0.f;
        }
        // ---- load B tile ----
        const float* Ebase = E + ((size_t)c * N_EMB + k0) * DIM + d0;
#pragma unroll
        for (int r = 0; r < 8; r++) {
            int kk = r * 4 + brow;
            *(float4*)&Bs[kk][bcol] = *(const float4*)(Ebase + (size_t)kk * DIM + bcol);
        }
        __syncthreads();

        // ---- compute ----
#pragma unroll 8
        for (int kk = 0; kk < KB; kk++) {
            float4 af0 = *(const float4*)&As[kk][ty * 8];
            float4 af1 = *(const float4*)&As[kk][ty * 8 + 4];
            unsigned long long a[8];
            a[0] = pack2(af0.x, af0.x); a[1] = pack2(af0.y, af0.y);
            a[2] = pack2(af0.z, af0.z); a[3] = pack2(af0.w, af0.w);
            a[4] = pack2(af1.x, af1.x); a[5] = pack2(af1.y, af1.y);
            a[6] = pack2(af1.z, af1.z); a[7] = pack2(af1.w, af1.w);
            const unsigned long long* bp =
                (const unsigned long long*)&Bs[kk][tx * 8];
            unsigned long long b0 = bp[0], b1 = bp[1], b2 = bp[2], b3 = bp[3];
#pragma unroll
            for (int i = 0; i < 8; i++) {
                ffma2(acc[i][0], a[i], b0);
                ffma2(acc[i][1], a[i], b1);
                ffma2(acc[i][2], a[i], b2);
                ffma2(acc[i][3], a[i], b3);
            }
        }
        __syncthreads();
    }

    // ---- epilogue ----
#pragma unroll
    for (int i = 0; i < 8; i++) {
        int gmi = m0 + ty * 8 + i;
        if (gmi < cnt) {
            int b = g_order[s0 + gmi];
            float buf[8];
#pragma unroll
            for (int j = 0; j < 4; j++)
                unpack2(acc[i][j], buf[2 * j], buf[2 * j + 1]);
            float* orow = out + (size_t)b * DIM + d0 + tx * 8;
            *(float4*)(orow + 0) = make_float4(buf[0], buf[1], buf[2], buf[3]);
            *(float4*)(orow + 4) = make_float4(buf[4], buf[5], buf[6], buf[7]);
        }
    }
}

// ---------------- launch ----------------
extern "C" void kernel_launch(void* const* d_in, const int* in_sizes, int n_in,
                              void* d_out, int out_size)
{
    const int*   chrom    = (const int*)d_in[0];
    const float* position = (const float*)d_in[1];
    const float* embed    = (const float*)d_in[2];
    const float* centers  = (const float*)d_in[3];
    const float* logv     = (const float*)d_in[4];
    float*       out      = (float*)d_out;

    weights_kernel<<<BATCH, 128>>>(chrom, position, centers, logv);
    group_kernel<<<1, BATCH>>>(chrom);

    dim3 grid(DIM / N_TILE, BATCH / M_TILE, NUM_CHR);  // (4, 16, 24)
    gemm_kernel<<<grid, 128>>>(embed, out);
}

// round 3
// speedup vs baseline: 2.8866x; 2.8866x over previous
#include <cuda_runtime.h>
#include <cuda_bf16.h>
#include <cstdint>

#define NUM_CHR 24
#define N_EMB   512
#define DIM     512
#define BATCH   1024

#define MT 32          // samples per tile
#define NT 64          // dims per tile
#define KB 32          // k-chunk through smem
#define KSPLIT 4
#define KCH (N_EMB / KSPLIT)   // 128 k per split

typedef unsigned long long ull;

// ---------------- scratch (referenced from DEVICE code only!) ----------------
__device__ float g_W[BATCH * N_EMB];
__device__ int   g_order[BATCH];
__device__ int   g_start[NUM_CHR + 1];
__device__ float g_part[KSPLIT * BATCH * DIM];   // split-K partials (8 MB)

// ---------------- f32x2 helpers ----------------
__device__ __forceinline__ ull pack2(float lo, float hi) {
    ull r; asm("mov.b64 %0, {%1, %2};" : "=l"(r) : "f"(lo), "f"(hi)); return r;
}
__device__ __forceinline__ void unpack2(ull v, float& lo, float& hi) {
    asm("mov.b64 {%0, %1}, %2;" : "=f"(lo), "=f"(hi) : "l"(v));
}
__device__ __forceinline__ void ffma2(ull& d, ull a, ull b) {
    asm("fma.rn.f32x2 %0, %1, %2, %0;" : "+l"(d) : "l"(a), "l"(b));
}

// ---------------- kernel 1: weights (warp per sample) ----------------
__global__ void __launch_bounds__(256) weights_kernel(
    const int* __restrict__ chrom,
    const float* __restrict__ pos,
    const float* __restrict__ centers,
    const float* __restrict__ logv)
{
    int warp = threadIdx.x >> 5, lane = threadIdx.x & 31;
    int b = blockIdx.x * 8 + warp;
    int c = chrom[b];
    float p = pos[b];

    const float* crow = centers + (size_t)c * N_EMB;
    const float* vrow = logv + (size_t)c * N_EMB;
    int n0 = lane * 16;

    float w[16];
    float s = 0.f;
#pragma unroll
    for (int i = 0; i < 4; i++) {
        float4 cc = *(const float4*)(crow + n0 + i * 4);
        float4 lv = *(const float4*)(vrow + n0 + i * 4);
        float d, iv;
        d = p - cc.x; iv = __expf(-lv.x); w[i*4+0] = __expf(-0.5f * d * d * iv);
        d = p - cc.y; iv = __expf(-lv.y); w[i*4+1] = __expf(-0.5f * d * d * iv);
        d = p - cc.z; iv = __expf(-lv.z); w[i*4+2] = __expf(-0.5f * d * d * iv);
        d = p - cc.w; iv = __expf(-lv.w); w[i*4+3] = __expf(-0.5f * d * d * iv);
        s += w[i*4+0] + w[i*4+1] + w[i*4+2] + w[i*4+3];
    }
#pragma unroll
    for (int off = 16; off > 0; off >>= 1)
        s += __shfl_xor_sync(0xffffffffu, s, off);
    float inv = 1.f / s;

    float* wrow = g_W + (size_t)b * N_EMB + n0;
#pragma unroll
    for (int i = 0; i < 4; i++) {
        *(float4*)(wrow + i * 4) = make_float4(w[i*4+0] * inv, w[i*4+1] * inv,
                                               w[i*4+2] * inv, w[i*4+3] * inv);
    }
}

// ---------------- kernel 2: group samples by chromosome ----------------
__global__ void group_kernel(const int* __restrict__ chrom)
{
    __shared__ int cnt[NUM_CHR];
    __shared__ int base[NUM_CHR];
    int t = threadIdx.x;
    if (t < NUM_CHR) cnt[t] = 0;
    __syncthreads();
    int c = chrom[t];
    int r = atomicAdd(&cnt[c], 1);
    __syncthreads();
    if (t == 0) {
        int acc = 0;
        for (int i = 0; i < NUM_CHR; i++) {
            base[i] = acc;
            g_start[i] = acc;
            acc += cnt[i];
        }
        g_start[NUM_CHR] = acc;
    }
    __syncthreads();
    g_order[base[c] + r] = t;
}

// ---------------- kernel 3: grouped GEMM with split-K ----------------
// Block: M32 x N64 x K128. 128 threads, micro-tile 4m x 4n (f32x2 accum).
__global__ void __launch_bounds__(128) gemm_kernel(const float* __restrict__ E)
{
    int c  = blockIdx.z;
    int nt = blockIdx.x;
    int ks = blockIdx.y >> 2;
    int mt = blockIdx.y & 3;

    int s0  = g_start[c];
    int cnt = g_start[c + 1] - s0;
    int m0  = mt * MT;
    if (m0 >= cnt) return;

    __shared__ __align__(16) ull   As[KB][MT];   // packed (a,a) pairs
    __shared__ __align__(16) float Bs[KB][NT];
    __shared__ int sord[MT];

    int tid = threadIdx.x;
    int d0  = nt * NT;

    if (tid < MT) {
        int g = m0 + tid;
        sord[tid] = (g < cnt) ? g_order[s0 + g] : -1;
    }
    __syncthreads();

    // A-load assignment: thread -> (m row, 8-wide k segment)
    int am = tid >> 2;             // 0..31
    int ak = (tid & 3) * 8;        // 0,8,16,24
    int samp = sord[am];
    const float* wrow = (samp >= 0) ? (g_W + (size_t)samp * N_EMB) : g_W;

    // B-load assignment: thread -> (k row, 16-wide col segment)
    int bk = tid >> 2;             // 0..31
    int bc = (tid & 3) * 16;       // 0,16,32,48

    // micro-tile coords
    int tx = tid & 15;             // n: d0 + tx*4
    int ty = tid >> 4;             // m: ty*4

    ull acc[4][2];
#pragma unroll
    for (int i = 0; i < 4; i++) { acc[i][0] = 0ull; acc[i][1] = 0ull; }

    int kbase = ks * KCH;
    for (int k0 = kbase; k0 < kbase + KCH; k0 += KB) {
        // A tile (pre-packed f32x2)
        if (samp >= 0) {
            float4 v0 = *(const float4*)(wrow + k0 + ak + 0);
            float4 v1 = *(const float4*)(wrow + k0 + ak + 4);
            As[ak + 0][am] = pack2(v0.x, v0.x);
            As[ak + 1][am] = pack2(v0.y, v0.y);
            As[ak + 2][am] = pack2(v0.z, v0.z);
            As[ak + 3][am] = pack2(v0.w, v0.w);
            As[ak + 4][am] = pack2(v1.x, v1.x);
            As[ak + 5][am] = pack2(v1.y, v1.y);
            As[ak + 6][am] = pack2(v1.z, v1.z);
            As[ak + 7][am] = pack2(v1.w, v1.w);
        } else {
#pragma unroll
            for (int j = 0; j < 8; j++) As[ak + j][am] = 0ull;
        }
        // B tile
        const float* Eb = E + ((size_t)c * N_EMB + k0 + bk) * DIM + d0 + bc;
        float4 e0 = *(const float4*)(Eb + 0);
        float4 e1 = *(const float4*)(Eb + 4);
        float4 e2 = *(const float4*)(Eb + 8);
        float4 e3 = *(const float4*)(Eb + 12);
        *(float4*)&Bs[bk][bc + 0]  = e0;
        *(float4*)&Bs[bk][bc + 4]  = e1;
        *(float4*)&Bs[bk][bc + 8]  = e2;
        *(float4*)&Bs[bk][bc + 12] = e3;
        __syncthreads();

#pragma unroll
        for (int kk = 0; kk < KB; kk++) {
            const ull* ap = &As[kk][ty * 4];
            ull a0 = ap[0], a1 = ap[1], a2 = ap[2], a3 = ap[3];
            const ull* bp = (const ull*)&Bs[kk][tx * 4];
            ull b0 = bp[0], b1 = bp[1];
            ffma2(acc[0][0], a0, b0); ffma2(acc[0][1], a0, b1);
            ffma2(acc[1][0], a1, b0); ffma2(acc[1][1], a1, b1);
            ffma2(acc[2][0], a2, b0); ffma2(acc[2][1], a2, b1);
            ffma2(acc[3][0], a3, b0); ffma2(acc[3][1], a3, b1);
        }
        __syncthreads();
    }

    // epilogue -> split-K partials (device symbol, referenced in device code)
    float* pbase = g_part + (size_t)ks * BATCH * DIM;
#pragma unroll
    for (int i = 0; i < 4; i++) {
        int gmi = m0 + ty * 4 + i;
        if (gmi < cnt) {
            int b = sord[ty * 4 + i];
            float x0, x1, x2, x3;
            unpack2(acc[i][0], x0, x1);
            unpack2(acc[i][1], x2, x3);
            *(float4*)(pbase + (size_t)b * DIM + d0 + tx * 4) =
                make_float4(x0, x1, x2, x3);
        }
    }
}

// ---------------- kernel 4: fixed-order split-K reduce ----------------
__global__ void __launch_bounds__(256) reduce_kernel(float* __restrict__ out)
{
    int i = (blockIdx.x * 256 + threadIdx.x) * 4;
    const size_t S = (size_t)BATCH * DIM;
    float4 a = *(const float4*)(g_part + i);
    float4 b = *(const float4*)(g_part + S + i);
    float4 c = *(const float4*)(g_part + 2 * S + i);
    float4 d = *(const float4*)(g_part + 3 * S + i);
    *(float4*)(out + i) = make_float4(
        (a.x + b.x) + (c.x + d.x),
        (a.y + b.y) + (c.y + d.y),
        (a.z + b.z) + (c.z + d.z),
        (a.w + b.w) + (c.w + d.w));
}

// ---------------- launch ----------------
extern "C" void kernel_launch(void* const* d_in, const int* in_sizes, int n_in,
                              void* d_out, int out_size)
{
    const int*   chrom    = (const int*)d_in[0];
    const float* position = (const float*)d_in[1];
    const float* embed    = (const float*)d_in[2];
    const float* centers  = (const float*)d_in[3];
    const float* logv     = (const float*)d_in[4];
    float*       out      = (float*)d_out;

    weights_kernel<<<BATCH / 8, 256>>>(chrom, position, centers, logv);
    group_kernel<<<1, BATCH>>>(chrom);

    dim3 grid(DIM / NT, KSPLIT * 4, NUM_CHR);   // (8, 16, 24)
    gemm_kernel<<<grid, 128>>>(embed);

    reduce_kernel<<<BATCH * DIM / (256 * 4), 256>>>(out);
}